// round 14
// baseline (speedup 1.0000x reference)
#include <cuda_runtime.h>
#include <cuda_fp16.h>
#include <cstdint>

#define MDIM 4096
#define KDIM 4096
#define NDIM 4096
#define BB   32
#define NBCOLS 128
#define KBROWS 128
#define BM   256
#define THREADS 256
#define MAXBLK (KBROWS * NBCOLS)
#define XCONV_BLOCKS (KBROWS * 32)     // 4096

// ---------------- device scratch ----------------
__device__ int g_cnt[NBCOLS];
__device__ int g_listn[NBCOLS * KBROWS];
__device__ int g_listi[NBCOLS * KBROWS];
// w fragments fp16: [n][nt][lane] -> uint4 = (kc0:r0,r1, kc1:r0,r1)
__device__ uint4 g_wf[(size_t)MAXBLK * 128];
// x A-fragments fp16: [i][t16][kc][lane] -> uint4
__device__ uint4 g_xf[(size_t)KBROWS * 256 * 2 * 32];

// ---------------- fused prep kernel ----------------
__global__ __launch_bounds__(THREADS) void prep_kernel(
    const float* __restrict__ x,
    const float* __restrict__ w,
    const int*  __restrict__ idx_i,
    const int*  __restrict__ idx_j,
    int nnz)
{
    __shared__ float sbuf[128 * 32];
    const int bid = blockIdx.x;
    const int tid = threadIdx.x;

    if (bid < XCONV_BLOCKS) {
        // ---------- xconv: fp32 -> fp16 A fragments ----------
        const int i  = bid >> 5;
        const int mc = bid & 31;
        const float4* X4 = reinterpret_cast<const float4*>(x);
        float4* XS4 = reinterpret_cast<float4*>(sbuf);
        #pragma unroll
        for (int t = 0; t < 4; ++t) {
            int idx = tid + t * THREADS;
            int r = idx >> 3, c4 = idx & 7;
            XS4[r * 8 + c4] = X4[(size_t)(mc * 128 + r) * (KDIM / 4) + i * 8 + c4];
        }
        __syncthreads();
        #pragma unroll
        for (int it0 = 0; it0 < 2; ++it0) {
            int it   = tid + it0 * THREADS;
            int lane = it & 31;
            int kc   = (it >> 5) & 1;
            int t16  = it >> 6;
            int gid  = lane >> 2, tig = lane & 3;
            int r0 = t16 * 16 + gid, r1 = r0 + 8;
            int c0 = kc * 16 + 2 * tig;
            int c2 = c0 + 8;
            float f[8];
            f[0] = sbuf[r0 * 32 + c0];  f[1] = sbuf[r0 * 32 + c0 + 1];
            f[2] = sbuf[r1 * 32 + c0];  f[3] = sbuf[r1 * 32 + c0 + 1];
            f[4] = sbuf[r0 * 32 + c2];  f[5] = sbuf[r0 * 32 + c2 + 1];
            f[6] = sbuf[r1 * 32 + c2];  f[7] = sbuf[r1 * 32 + c2 + 1];
            uint4 hv;
            uint32_t* hw = reinterpret_cast<uint32_t*>(&hv);
            #pragma unroll
            for (int p = 0; p < 4; ++p) {
                __half2 hp = __float22half2_rn(make_float2(f[2 * p], f[2 * p + 1]));
                hw[p] = *reinterpret_cast<uint32_t*>(&hp);
            }
            g_xf[((size_t)(i * 256 + mc * 8 + t16) * 2 + kc) * 32 + lane] = hv;
        }
    } else if (bid < XCONV_BLOCKS + nnz) {
        // ---------- wconv: fp32 -> fp16 B fragments ----------
        const int n = bid - XCONV_BLOCKS;
        const float* wn = w + (size_t)n * (BB * BB);
        #pragma unroll
        for (int q = 0; q < 4; ++q) sbuf[tid + q * THREADS] = wn[tid + q * THREADS];
        __syncthreads();
        uint32_t* WF = reinterpret_cast<uint32_t*>(g_wf);
        #pragma unroll
        for (int q = 0; q < 2; ++q) {
            int oi   = tid + q * THREADS;        // 0..511
            int nt   = oi >> 7;
            int lane = (oi >> 2) & 31;
            int word = oi & 3;
            int kc   = word >> 1, reg = word & 1;
            int gid  = lane >> 2, tig = lane & 3;
            int c  = nt * 8 + gid;
            int k0 = kc * 16 + 2 * tig + reg * 8;
            __half2 out = __float22half2_rn(make_float2(sbuf[k0 * BB + c],
                                                        sbuf[(k0 + 1) * BB + c]));
            WF[(size_t)n * 512 + oi] = *reinterpret_cast<uint32_t*>(&out);
        }
    } else {
        // ---------- bucket: one warp per output column ----------
        const int blk  = bid - XCONV_BLOCKS - nnz;
        const int j    = blk * 8 + (tid >> 5);
        const int lane = tid & 31;
        if (j < NBCOLS) {
            int cnt = 0;
            for (int base = 0; base < nnz; base += 32) {
                int n = base + lane;
                bool hit = (n < nnz) && (idx_j[n] == j);
                unsigned m = __ballot_sync(0xFFFFFFFFu, hit);
                if (hit) {
                    int pos = cnt + __popc(m & ((1u << lane) - 1u));
                    g_listn[j * KBROWS + pos] = n;
                    g_listi[j * KBROWS + pos] = idx_i[n];
                }
                cnt += __popc(m);
            }
            if (lane == 0) g_cnt[j] = cnt;
        }
    }
}

// ---------------- main HMMA kernel: fp16, register-double-buffered prefetch ----------------
__global__ __launch_bounds__(THREADS) void bsmm_mma_kernel(float* __restrict__ y)
{
    __shared__ int s_n[KBROWS];
    __shared__ int s_i[KBROWS];

    const int j    = blockIdx.x;
    const int m0   = blockIdx.y * BM;
    const int tid  = threadIdx.x;
    const int wid  = tid >> 5;
    const int lane = tid & 31;
    const int gid  = lane >> 2;
    const int tig  = lane & 3;

    const int t16base = (m0 >> 4) + wid * 2;

    const int cnt = g_cnt[j];
    if (tid < cnt) {
        s_n[tid] = g_listn[j * KBROWS + tid];
        s_i[tid] = g_listi[j * KBROWS + tid];
    }
    __syncthreads();

    float acc[2][4][4];
    #pragma unroll
    for (int s = 0; s < 2; ++s)
        #pragma unroll
        for (int t = 0; t < 4; ++t)
            #pragma unroll
            for (int r = 0; r < 4; ++r) acc[s][t][r] = 0.0f;

    // double-buffered fragment registers
    uint4 xa[2][2][2];   // [buf][s][kc]
    uint4 wb[2][4];      // [buf][nt]

    if (cnt > 0) {
        const int n0 = s_n[0], i0 = s_i[0];
        #pragma unroll
        for (int s = 0; s < 2; ++s)
            #pragma unroll
            for (int kc = 0; kc < 2; ++kc)
                xa[0][s][kc] = __ldg(&g_xf[((size_t)(i0 * 256 + t16base + s) * 2 + kc) * 32 + lane]);
        const uint4* wf0 = g_wf + (size_t)n0 * 128 + lane;
        #pragma unroll
        for (int nt = 0; nt < 4; ++nt) wb[0][nt] = __ldg(&wf0[nt * 32]);
    }

    for (int e = 0; e < cnt; ++e) {
        const int cur = e & 1, nxt = cur ^ 1;

        // ---- prefetch iter e+1 into the other buffer (before MMAs) ----
        if (e + 1 < cnt) {
            const int n1 = s_n[e + 1], i1 = s_i[e + 1];
            #pragma unroll
            for (int s = 0; s < 2; ++s)
                #pragma unroll
                for (int kc = 0; kc < 2; ++kc)
                    xa[nxt][s][kc] = __ldg(&g_xf[((size_t)(i1 * 256 + t16base + s) * 2 + kc) * 32 + lane]);
            const uint4* wf1 = g_wf + (size_t)n1 * 128 + lane;
            #pragma unroll
            for (int nt = 0; nt < 4; ++nt) wb[nxt][nt] = __ldg(&wf1[nt * 32]);
        }

        // ---- 16 MMAs on current buffer (same-acc revisit distance = 8) ----
        #pragma unroll
        for (int kc = 0; kc < 2; ++kc) {
            #pragma unroll
            for (int nt = 0; nt < 4; ++nt) {
                uint32_t b0 = kc ? wb[cur][nt].z : wb[cur][nt].x;
                uint32_t b1 = kc ? wb[cur][nt].w : wb[cur][nt].y;
                #pragma unroll
                for (int s = 0; s < 2; ++s) {
                    const uint4& A = xa[cur][s][kc];
                    float* d = acc[s][nt];
                    asm volatile(
                        "mma.sync.aligned.m16n8k16.row.col.f32.f16.f16.f32 "
                        "{%0,%1,%2,%3}, {%4,%5,%6,%7}, {%8,%9}, {%0,%1,%2,%3};"
                        : "+f"(d[0]), "+f"(d[1]), "+f"(d[2]), "+f"(d[3])
                        : "r"(A.x), "r"(A.y), "r"(A.z), "r"(A.w),
                          "r"(b0), "r"(b1));
                }
            }
        }
    }

    // ---- epilogue ----
    #pragma unroll
    for (int s = 0; s < 2; ++s) {
        #pragma unroll
        for (int nt = 0; nt < 4; ++nt) {
            const float* d = acc[s][nt];
            int row0 = m0 + wid * 32 + s * 16 + gid;
            int col  = j * BB + nt * 8 + tig * 2;
            *reinterpret_cast<float2*>(&y[(size_t)row0 * NDIM + col]) =
                make_float2(d[0], d[1]);
            *reinterpret_cast<float2*>(&y[(size_t)(row0 + 8) * NDIM + col]) =
                make_float2(d[2], d[3]);
        }
    }
}

extern "C" void kernel_launch(void* const* d_in, const int* in_sizes, int n_in,
                              void* d_out, int out_size)
{
    const float* x     = (const float*)d_in[0];
    const float* w     = (const float*)d_in[1];
    const int*   idx_i = (const int*)d_in[2];
    const int*   idx_j = (const int*)d_in[3];
    float*       y     = (float*)d_out;
    const int    nnz   = in_sizes[2];

    prep_kernel<<<XCONV_BLOCKS + nnz + 16, THREADS>>>(x, w, idx_i, idx_j, nnz);

    dim3 grid(NBCOLS, MDIM / BM);
    bsmm_mma_kernel<<<grid, THREADS>>>(y);
}

// round 15
// speedup vs baseline: 2.1278x; 2.1278x over previous
#include <cuda_runtime.h>
#include <cuda_fp16.h>
#include <cstdint>

#define MDIM 4096
#define KDIM 4096
#define NDIM 4096
#define BB   32
#define NBCOLS 128
#define KBROWS 128
#define BM   256
#define THREADS 256
#define MAXBLK (KBROWS * NBCOLS)
#define XCONV_BLOCKS (KBROWS * 32)     // 4096

// ---------------- device scratch ----------------
__device__ int g_cnt[NBCOLS];
__device__ int g_listn[NBCOLS * KBROWS];
__device__ int g_listi[NBCOLS * KBROWS];
// w fragments fp16: [n][nt][lane] -> uint4 = (kc0:r0,r1, kc1:r0,r1)
__device__ uint4 g_wf[(size_t)MAXBLK * 128];
// x A-fragments fp16: [i][t16][kc][lane] -> uint4
__device__ uint4 g_xf[(size_t)KBROWS * 256 * 2 * 32];

// ---------------- fused prep kernel ----------------
__global__ __launch_bounds__(THREADS) void prep_kernel(
    const float* __restrict__ x,
    const float* __restrict__ w,
    const int*  __restrict__ idx_i,
    const int*  __restrict__ idx_j,
    int nnz)
{
    __shared__ float sbuf[128 * 32];
    const int bid = blockIdx.x;
    const int tid = threadIdx.x;

    if (bid < XCONV_BLOCKS) {
        // ---------- xconv: fp32 -> fp16 A fragments ----------
        const int i  = bid >> 5;
        const int mc = bid & 31;
        const float4* X4 = reinterpret_cast<const float4*>(x);
        float4* XS4 = reinterpret_cast<float4*>(sbuf);
        #pragma unroll
        for (int t = 0; t < 4; ++t) {
            int idx = tid + t * THREADS;
            int r = idx >> 3, c4 = idx & 7;
            XS4[r * 8 + c4] = X4[(size_t)(mc * 128 + r) * (KDIM / 4) + i * 8 + c4];
        }
        __syncthreads();
        #pragma unroll
        for (int it0 = 0; it0 < 2; ++it0) {
            int it   = tid + it0 * THREADS;
            int lane = it & 31;
            int kc   = (it >> 5) & 1;
            int t16  = it >> 6;
            int gid  = lane >> 2, tig = lane & 3;
            int r0 = t16 * 16 + gid, r1 = r0 + 8;
            int c0 = kc * 16 + 2 * tig;
            int c2 = c0 + 8;
            float f[8];
            f[0] = sbuf[r0 * 32 + c0];  f[1] = sbuf[r0 * 32 + c0 + 1];
            f[2] = sbuf[r1 * 32 + c0];  f[3] = sbuf[r1 * 32 + c0 + 1];
            f[4] = sbuf[r0 * 32 + c2];  f[5] = sbuf[r0 * 32 + c2 + 1];
            f[6] = sbuf[r1 * 32 + c2];  f[7] = sbuf[r1 * 32 + c2 + 1];
            uint4 hv;
            uint32_t* hw = reinterpret_cast<uint32_t*>(&hv);
            #pragma unroll
            for (int p = 0; p < 4; ++p) {
                __half2 hp = __float22half2_rn(make_float2(f[2 * p], f[2 * p + 1]));
                hw[p] = *reinterpret_cast<uint32_t*>(&hp);
            }
            g_xf[((size_t)(i * 256 + mc * 8 + t16) * 2 + kc) * 32 + lane] = hv;
        }
    } else if (bid < XCONV_BLOCKS + nnz) {
        // ---------- wconv: fp32 -> fp16 B fragments ----------
        const int n = bid - XCONV_BLOCKS;
        const float* wn = w + (size_t)n * (BB * BB);
        #pragma unroll
        for (int q = 0; q < 4; ++q) sbuf[tid + q * THREADS] = wn[tid + q * THREADS];
        __syncthreads();
        uint32_t* WF = reinterpret_cast<uint32_t*>(g_wf);
        #pragma unroll
        for (int q = 0; q < 2; ++q) {
            int oi   = tid + q * THREADS;        // 0..511
            int nt   = oi >> 7;
            int lane = (oi >> 2) & 31;
            int word = oi & 3;
            int kc   = word >> 1, reg = word & 1;
            int gid  = lane >> 2, tig = lane & 3;
            int c  = nt * 8 + gid;
            int k0 = kc * 16 + 2 * tig + reg * 8;
            __half2 out = __float22half2_rn(make_float2(sbuf[k0 * BB + c],
                                                        sbuf[(k0 + 1) * BB + c]));
            WF[(size_t)n * 512 + oi] = *reinterpret_cast<uint32_t*>(&out);
        }
    } else {
        // ---------- bucket: one warp per output column ----------
        const int blk  = bid - XCONV_BLOCKS - nnz;
        const int j    = blk * 8 + (tid >> 5);
        const int lane = tid & 31;
        if (j < NBCOLS) {
            int cnt = 0;
            for (int base = 0; base < nnz; base += 32) {
                int n = base + lane;
                bool hit = (n < nnz) && (idx_j[n] == j);
                unsigned m = __ballot_sync(0xFFFFFFFFu, hit);
                if (hit) {
                    int pos = cnt + __popc(m & ((1u << lane) - 1u));
                    g_listn[j * KBROWS + pos] = n;
                    g_listi[j * KBROWS + pos] = idx_i[n];
                }
                cnt += __popc(m);
            }
            if (lane == 0) g_cnt[j] = cnt;
        }
    }
}

// ---------------- main HMMA kernel: fp16, STATIC register double-buffering ----------------
__global__ __launch_bounds__(THREADS) void bsmm_mma_kernel(float* __restrict__ y)
{
    __shared__ int s_n[KBROWS];
    __shared__ int s_i[KBROWS];

    const int j    = blockIdx.x;
    const int m0   = blockIdx.y * BM;
    const int tid  = threadIdx.x;
    const int wid  = tid >> 5;
    const int lane = tid & 31;
    const int gid  = lane >> 2;
    const int tig  = lane & 3;

    const int t16base = (m0 >> 4) + wid * 2;

    const int cnt = g_cnt[j];
    if (tid < cnt) {
        s_n[tid] = g_listn[j * KBROWS + tid];
        s_i[tid] = g_listi[j * KBROWS + tid];
    }
    __syncthreads();

    float acc[2][4][4];
    #pragma unroll
    for (int s = 0; s < 2; ++s)
        #pragma unroll
        for (int t = 0; t < 4; ++t)
            #pragma unroll
            for (int r = 0; r < 4; ++r) acc[s][t][r] = 0.0f;

    // two statically-named fragment buffer sets (always register-resident)
    uint4 xa0[2][2], xa1[2][2];   // [s][kc]
    uint4 wb0[4],    wb1[4];      // [nt]

    auto prefetch0 = [&](int e) {
        const int n = s_n[e], i = s_i[e];
        #pragma unroll
        for (int s = 0; s < 2; ++s)
            #pragma unroll
            for (int kc = 0; kc < 2; ++kc)
                xa0[s][kc] = __ldg(&g_xf[((size_t)(i * 256 + t16base + s) * 2 + kc) * 32 + lane]);
        const uint4* wf = g_wf + (size_t)n * 128 + lane;
        #pragma unroll
        for (int nt = 0; nt < 4; ++nt) wb0[nt] = __ldg(&wf[nt * 32]);
    };
    auto prefetch1 = [&](int e) {
        const int n = s_n[e], i = s_i[e];
        #pragma unroll
        for (int s = 0; s < 2; ++s)
            #pragma unroll
            for (int kc = 0; kc < 2; ++kc)
                xa1[s][kc] = __ldg(&g_xf[((size_t)(i * 256 + t16base + s) * 2 + kc) * 32 + lane]);
        const uint4* wf = g_wf + (size_t)n * 128 + lane;
        #pragma unroll
        for (int nt = 0; nt < 4; ++nt) wb1[nt] = __ldg(&wf[nt * 32]);
    };
    auto do_mma = [&](uint4 (&xa)[2][2], uint4 (&wb)[4]) {
        #pragma unroll
        for (int kc = 0; kc < 2; ++kc) {
            #pragma unroll
            for (int nt = 0; nt < 4; ++nt) {
                uint32_t b0 = kc ? wb[nt].z : wb[nt].x;
                uint32_t b1 = kc ? wb[nt].w : wb[nt].y;
                #pragma unroll
                for (int s = 0; s < 2; ++s) {
                    const uint4& A = xa[s][kc];
                    float* d = acc[s][nt];
                    asm volatile(
                        "mma.sync.aligned.m16n8k16.row.col.f32.f16.f16.f32 "
                        "{%0,%1,%2,%3}, {%4,%5,%6,%7}, {%8,%9}, {%0,%1,%2,%3};"
                        : "+f"(d[0]), "+f"(d[1]), "+f"(d[2]), "+f"(d[3])
                        : "r"(A.x), "r"(A.y), "r"(A.z), "r"(A.w),
                          "r"(b0), "r"(b1));
                }
            }
        }
    };

    int e = 0;
    if (cnt > 0) prefetch0(0);
    while (e + 1 < cnt) {
        prefetch1(e + 1);
        do_mma(xa0, wb0);
        if (e + 2 < cnt) prefetch0(e + 2);
        do_mma(xa1, wb1);
        e += 2;
    }
    if (e < cnt) do_mma(xa0, wb0);   // tail (cnt odd)

    // ---- epilogue ----
    #pragma unroll
    for (int s = 0; s < 2; ++s) {
        #pragma unroll
        for (int nt = 0; nt < 4; ++nt) {
            const float* d = acc[s][nt];
            int row0 = m0 + wid * 32 + s * 16 + gid;
            int col  = j * BB + nt * 8 + tig * 2;
            *reinterpret_cast<float2*>(&y[(size_t)row0 * NDIM + col]) =
                make_float2(d[0], d[1]);
            *reinterpret_cast<float2*>(&y[(size_t)(row0 + 8) * NDIM + col]) =
                make_float2(d[2], d[3]);
        }
    }
}

extern "C" void kernel_launch(void* const* d_in, const int* in_sizes, int n_in,
                              void* d_out, int out_size)
{
    const float* x     = (const float*)d_in[0];
    const float* w     = (const float*)d_in[1];
    const int*   idx_i = (const int*)d_in[2];
    const int*   idx_j = (const int*)d_in[3];
    float*       y     = (float*)d_out;
    const int    nnz   = in_sizes[2];

    prep_kernel<<<XCONV_BLOCKS + nnz + 16, THREADS>>>(x, w, idx_i, idx_j, nnz);

    dim3 grid(NBCOLS, MDIM / BM);
    bsmm_mma_kernel<<<grid, THREADS>>>(y);
}